// round 7
// baseline (speedup 1.0000x reference)
#include <cuda_runtime.h>
#include <cuda_bf16.h>
#include <cstdint>

// Problem constants
#define BB 8
#define SS 1024
#define DD 768
#define HH 12
#define HD 64

// Scratch: projected q,k,v in (B,H,S,HD) layout + rel_attn (B,S,S) + row sums
__device__ float g_q[BB * HH * SS * HD];      // 24 MB
__device__ float g_k[BB * HH * SS * HD];      // 24 MB
__device__ float g_v[BB * HH * SS * HD];      // 24 MB
__device__ float g_rel[BB * SS * SS];         // 32 MB
__device__ float g_l[BB * HH * SS];           // 384 KB (softmax denominators)

// ---- packed f32x2 helpers (Blackwell FFMA2 fast path) ----------------------
__device__ __forceinline__ unsigned long long ffma2(
    unsigned long long a, unsigned long long b, unsigned long long c)
{
    unsigned long long d;
    asm("fma.rn.f32x2 %0, %1, %2, %3;" : "=l"(d) : "l"(a), "l"(b), "l"(c));
    return d;
}
__device__ __forceinline__ unsigned long long bcast2(float x)
{
    unsigned long long r;
    asm("mov.b64 %0, {%1, %1};" : "=l"(r) : "r"(__float_as_uint(x)));
    return r;
}
__device__ __forceinline__ float2 unpack2(unsigned long long v)
{
    float2 f;
    asm("mov.b64 {%0, %1}, %2;" : "=f"(f.x), "=f"(f.y) : "l"(v));
    return f;
}

// ---------------------------------------------------------------------------
// Projection GEMM: Y[i,j] = sum_k X[i,k] * W[j,k] + b[j]
// Output written directly in (B,H,S,HD) layout.
// 128x128x8 tiles, 256 threads, 8x8 micro-tile computed as 4x8 f32x2 pairs.
// Register double-buffering on the gmem tile loads.
// ---------------------------------------------------------------------------
__global__ __launch_bounds__(256) void proj_kernel(
    const float* __restrict__ X, const float* __restrict__ W,
    const float* __restrict__ bias, float* __restrict__ out)
{
    __shared__ float As[8][132];
    __shared__ float Bs[8][132];

    const int t  = threadIdx.x;
    const int bm = blockIdx.y * 128;
    const int bn = blockIdx.x * 128;
    const int tx = t & 15;
    const int ty = t >> 4;
    const int lr = t >> 1;
    const int lc = (t & 1) * 4;

    unsigned long long acc2[4][8];
#pragma unroll
    for (int i = 0; i < 4; i++)
#pragma unroll
        for (int j = 0; j < 8; j++) acc2[i][j] = 0ull;

    const float* Aptr = X + (size_t)(bm + lr) * DD + lc;
    const float* Bptr = W + (size_t)(bn + lr) * DD + lc;

    float4 a4 = *(const float4*)(Aptr);
    float4 b4 = *(const float4*)(Bptr);

    for (int k0 = 0; k0 < DD; k0 += 8) {
        As[lc + 0][lr] = a4.x; As[lc + 1][lr] = a4.y;
        As[lc + 2][lr] = a4.z; As[lc + 3][lr] = a4.w;
        Bs[lc + 0][lr] = b4.x; Bs[lc + 1][lr] = b4.y;
        Bs[lc + 2][lr] = b4.z; Bs[lc + 3][lr] = b4.w;
        __syncthreads();

        // prefetch next gmem tile into registers (overlaps with compute)
        if (k0 + 8 < DD) {
            a4 = *(const float4*)(Aptr + k0 + 8);
            b4 = *(const float4*)(Bptr + k0 + 8);
        }

#pragma unroll
        for (int k = 0; k < 8; k++) {
            const ulonglong2 a01 = *(const ulonglong2*)&As[k][ty * 8];
            const ulonglong2 a23 = *(const ulonglong2*)&As[k][ty * 8 + 4];
            unsigned long long a2[4] = {a01.x, a01.y, a23.x, a23.y};
            float bs[8];
            *(float4*)&bs[0] = *(const float4*)&Bs[k][tx * 8];
            *(float4*)&bs[4] = *(const float4*)&Bs[k][tx * 8 + 4];
#pragma unroll
            for (int j = 0; j < 8; j++) {
                const unsigned long long bb = bcast2(bs[j]);
#pragma unroll
                for (int i2 = 0; i2 < 4; i2++)
                    acc2[i2][j] = ffma2(a2[i2], bb, acc2[i2][j]);
            }
        }
        __syncthreads();
    }

#pragma unroll
    for (int i2 = 0; i2 < 4; i2++) {
#pragma unroll
        for (int j = 0; j < 8; j++) {
            const float2 v = unpack2(acc2[i2][j]);
            const int col = bn + tx * 8 + j;
            const int h   = col >> 6;
            const int d   = col & 63;
            const float bia = bias[col];
            const int row0 = bm + ty * 8 + i2 * 2;
            const int b0 = row0 >> 10, s0 = row0 & 1023;
            out[(((size_t)b0 * HH + h) * SS + s0) * HD + d] = v.x + bia;
            const int row1 = row0 + 1;
            const int b1 = row1 >> 10, s1 = row1 & 1023;
            out[(((size_t)b1 * HH + h) * SS + s1) * HD + d] = v.y + bia;
        }
    }
}

// ---------------------------------------------------------------------------
// rel_attn = softmax over k of (mask ? rel : -1e4).  (head-independent)
// ---------------------------------------------------------------------------
__global__ __launch_bounds__(256) void rel_softmax_kernel(
    const float* __restrict__ rel, const unsigned int* __restrict__ mask,
    float* __restrict__ outr)
{
    const int row = blockIdx.x;
    const float* r        = rel  + (size_t)row * SS;
    const unsigned int* m = mask + (size_t)row * SS;
    float* o              = outr + (size_t)row * SS;

    __shared__ float redmax[8], redsum[8];
    const int t = threadIdx.x;

    float v[4];
    float mx = -3.4e38f;
#pragma unroll
    for (int i = 0; i < 4; i++) {
        const int c = i * 256 + t;
        v[i] = m[c] ? r[c] : -1e4f;
        mx = fmaxf(mx, v[i]);
    }
#pragma unroll
    for (int o2 = 16; o2; o2 >>= 1) mx = fmaxf(mx, __shfl_xor_sync(0xffffffffu, mx, o2));
    if ((t & 31) == 0) redmax[t >> 5] = mx;
    __syncthreads();
    mx = redmax[0];
#pragma unroll
    for (int w = 1; w < 8; w++) mx = fmaxf(mx, redmax[w]);

    float sum = 0.f;
#pragma unroll
    for (int i = 0; i < 4; i++) {
        v[i] = __expf(v[i] - mx);
        sum += v[i];
    }
#pragma unroll
    for (int o2 = 16; o2; o2 >>= 1) sum += __shfl_xor_sync(0xffffffffu, sum, o2);
    if ((t & 31) == 0) redsum[t >> 5] = sum;
    __syncthreads();
    sum = 0.f;
#pragma unroll
    for (int w = 0; w < 8; w++) sum += redsum[w];
    const float inv = 1.f / sum;

#pragma unroll
    for (int i = 0; i < 4; i++) {
        const int c = i * 256 + t;
        o[c] = v[i] * inv;
    }
}

// ---------------------------------------------------------------------------
// QK kernel: one block per (b, h, q-tile of 128).
// S = Q Kt / 8, masked -> e = exp(S) (no max shift needed: |S| <~ 2),
// e written (unnormalized) into the prob output region as scratch;
// row sums accumulated into g_l.
// ---------------------------------------------------------------------------
#define QK_SMEM (2 * 64 * 132 * 4)

__global__ __launch_bounds__(256) void qk_kernel(
    const float* __restrict__ qg, const float* __restrict__ kg,
    const unsigned int* __restrict__ mask,
    float* __restrict__ eprob, float* __restrict__ lsum)
{
    extern __shared__ float sm[];
    float* Qs = sm;              // [64][132]
    float* Ks = sm + 64 * 132;   // [64][132]

    const int t  = threadIdx.x;
    const int ty = t >> 4;
    const int tx = t & 15;
    const int qt = blockIdx.x;
    const int h  = blockIdx.y;
    const int b  = blockIdx.z;
    const int bh = b * HH + h;
    const int qbase = qt * 128;

    const float* Qg = qg + ((size_t)bh * SS + qbase) * HD;
    const float* Kg = kg + (size_t)bh * SS * HD;

    const int lr = t >> 1;          // 0..127
    const int lc = (t & 1) * 4;     // 0 or 4

    // load Q tile transposed (conflict-free writes)
#pragma unroll
    for (int i = 0; i < 8; i++) {
        float4 v = *(const float4*)(Qg + (size_t)lr * HD + lc + 8 * i);
        Qs[(8 * i + lc + 0) * 132 + lr] = v.x;
        Qs[(8 * i + lc + 1) * 132 + lr] = v.y;
        Qs[(8 * i + lc + 2) * 132 + lr] = v.z;
        Qs[(8 * i + lc + 3) * 132 + lr] = v.w;
    }

    float lacc[8];
#pragma unroll
    for (int i = 0; i < 8; i++) lacc[i] = 0.f;

#pragma unroll 1
    for (int kt = 0; kt < 8; kt++) {
        __syncthreads();   // protect Ks reuse (also orders Qs fill on kt=0)
        const float* Kt = Kg + (size_t)kt * 128 * HD;
#pragma unroll
        for (int i = 0; i < 8; i++) {
            float4 v = *(const float4*)(Kt + (size_t)lr * HD + lc + 8 * i);
            Ks[(8 * i + lc + 0) * 132 + lr] = v.x;
            Ks[(8 * i + lc + 1) * 132 + lr] = v.y;
            Ks[(8 * i + lc + 2) * 132 + lr] = v.z;
            Ks[(8 * i + lc + 3) * 132 + lr] = v.w;
        }
        __syncthreads();

        unsigned long long acc2[4][8];
#pragma unroll
        for (int i = 0; i < 4; i++)
#pragma unroll
            for (int j = 0; j < 8; j++) acc2[i][j] = 0ull;

#pragma unroll
        for (int d = 0; d < 64; d++) {
            const ulonglong2 a01 = *(const ulonglong2*)&Qs[d * 132 + ty * 8];
            const ulonglong2 a23 = *(const ulonglong2*)&Qs[d * 132 + ty * 8 + 4];
            unsigned long long a2[4] = {a01.x, a01.y, a23.x, a23.y};
            float bs[8];
            *(float4*)&bs[0] = *(const float4*)&Ks[d * 132 + tx * 8];
            *(float4*)&bs[4] = *(const float4*)&Ks[d * 132 + tx * 8 + 4];
#pragma unroll
            for (int j = 0; j < 8; j++) {
                const unsigned long long bb = bcast2(bs[j]);
#pragma unroll
                for (int i2 = 0; i2 < 4; i2++)
                    acc2[i2][j] = ffma2(a2[i2], bb, acc2[i2][j]);
            }
        }

        // unpack to scalar tile
        float acc[8][8];
#pragma unroll
        for (int i2 = 0; i2 < 4; i2++)
#pragma unroll
            for (int j = 0; j < 8; j++) {
                const float2 v = unpack2(acc2[i2][j]);
                acc[i2 * 2 + 0][j] = v.x;
                acc[i2 * 2 + 1][j] = v.y;
            }

        // mask, exp, row partial sums, store e
#pragma unroll
        for (int i = 0; i < 8; i++) {
            const int q = qbase + ty * 8 + i;
            const unsigned int* mp =
                mask + ((size_t)b * SS + q) * SS + kt * 128 + tx * 8;
            const uint4 m0 = *(const uint4*)mp;
            const uint4 m1 = *(const uint4*)(mp + 4);
            float e[8];
            e[0] = m0.x ? 0.f : __expf(acc[i][0] * 0.125f);
            e[1] = m0.y ? 0.f : __expf(acc[i][1] * 0.125f);
            e[2] = m0.z ? 0.f : __expf(acc[i][2] * 0.125f);
            e[3] = m0.w ? 0.f : __expf(acc[i][3] * 0.125f);
            e[4] = m1.x ? 0.f : __expf(acc[i][4] * 0.125f);
            e[5] = m1.y ? 0.f : __expf(acc[i][5] * 0.125f);
            e[6] = m1.z ? 0.f : __expf(acc[i][6] * 0.125f);
            e[7] = m1.w ? 0.f : __expf(acc[i][7] * 0.125f);
            lacc[i] += e[0] + e[1] + e[2] + e[3] + e[4] + e[5] + e[6] + e[7];
            float* ep = eprob + ((size_t)bh * SS + q) * SS + kt * 128 + tx * 8;
            *(float4*)ep       = make_float4(e[0], e[1], e[2], e[3]);
            *(float4*)(ep + 4) = make_float4(e[4], e[5], e[6], e[7]);
        }
    }

    // reduce partial sums across the 16 tx lanes (within half-warp)
#pragma unroll
    for (int i = 0; i < 8; i++) {
        float v = lacc[i];
        v += __shfl_xor_sync(0xffffffffu, v, 1);
        v += __shfl_xor_sync(0xffffffffu, v, 2);
        v += __shfl_xor_sync(0xffffffffu, v, 4);
        v += __shfl_xor_sync(0xffffffffu, v, 8);
        lacc[i] = v;
    }
    if (tx == 0) {
#pragma unroll
        for (int i = 0; i < 8; i++)
            lsum[(size_t)bh * SS + qbase + ty * 8 + i] = lacc[i];
    }
}

// ---------------------------------------------------------------------------
// PV kernel: one block per (b, h, q-tile of 128).
// Reads e tile (from prob region), blends p = c0*e/l + l1*rel IN PLACE into
// prob, stages p transposed in SMEM, computes O = P @ V (128x1024x64 GEMM).
// ---------------------------------------------------------------------------
#define PV_SMEM ((64 * 132 + 64 * 68) * 4)

__global__ __launch_bounds__(256) void pv_kernel(
    const float* __restrict__ lsum, const float* __restrict__ relattn,
    const float* __restrict__ vg, const float* __restrict__ l1p,
    float* __restrict__ out, float* __restrict__ prob)
{
    extern __shared__ float sm[];
    float* Ps = sm;              // [64][132]  (k-major)
    float* Vs = sm + 64 * 132;   // [64][68]   (k-major, row-major d)

    const int t  = threadIdx.x;
    const int ty = t >> 4;
    const int tx = t & 15;
    const int qt = blockIdx.x;
    const int h  = blockIdx.y;
    const int b  = blockIdx.z;
    const int bh = b * HH + h;
    const int qbase = qt * 128;

    const float l1 = *l1p;
    const float c0 = 1.f - l1;

    const int lr  = t >> 1;
    const int lc4 = (t & 1) * 4;

    const float invl = 1.f / lsum[(size_t)bh * SS + qbase + lr];
    float* erow        = prob    + ((size_t)bh * SS + qbase + lr) * SS;
    const float* rrow  = relattn + ((size_t)b  * SS + qbase + lr) * SS;
    const float* Vbase = vg + (size_t)bh * SS * HD;

    unsigned long long oacc2[4][4];
#pragma unroll
    for (int i = 0; i < 4; i++)
#pragma unroll
        for (int j = 0; j < 4; j++) oacc2[i][j] = 0ull;

#pragma unroll 1
    for (int kt = 0; kt < 16; kt++) {
        __syncthreads();
        // blend + in-place prob write + transposed stage into Ps
#pragma unroll
        for (int i = 0; i < 8; i++) {
            const int kc = kt * 64 + lc4 + 8 * i;
            const float4 e4 = *(const float4*)(erow + kc);
            const float4 r4 = *(const float4*)(rrow + kc);
            float4 p4;
            p4.x = c0 * e4.x * invl + l1 * r4.x;
            p4.y = c0 * e4.y * invl + l1 * r4.y;
            p4.z = c0 * e4.z * invl + l1 * r4.z;
            p4.w = c0 * e4.w * invl + l1 * r4.w;
            *(float4*)(erow + kc) = p4;
            const int kk = lc4 + 8 * i;
            Ps[(kk + 0) * 132 + lr] = p4.x;
            Ps[(kk + 1) * 132 + lr] = p4.y;
            Ps[(kk + 2) * 132 + lr] = p4.z;
            Ps[(kk + 3) * 132 + lr] = p4.w;
        }
        // load V tile [64 k][64 d] row-major
        const float* Vt = Vbase + (size_t)kt * 64 * HD;
#pragma unroll
        for (int i = 0; i < 4; i++) {
            const int f  = i * 256 + t;
            const int vr = f >> 4;
            const int q4 = (f & 15) * 4;
            *(float4*)&Vs[vr * 68 + q4] = *(const float4*)(Vt + vr * HD + q4);
        }
        __syncthreads();

#pragma unroll
        for (int kk = 0; kk < 64; kk++) {
            const ulonglong2 a01 = *(const ulonglong2*)&Ps[kk * 132 + ty * 8];
            const ulonglong2 a23 = *(const ulonglong2*)&Ps[kk * 132 + ty * 8 + 4];
            unsigned long long a2[4] = {a01.x, a01.y, a23.x, a23.y};
            const float4 bv = *(const float4*)&Vs[kk * 68 + tx * 4];
            const unsigned long long b0 = bcast2(bv.x);
            const unsigned long long b1 = bcast2(bv.y);
            const unsigned long long b2 = bcast2(bv.z);
            const unsigned long long b3 = bcast2(bv.w);
#pragma unroll
            for (int i2 = 0; i2 < 4; i2++) {
                oacc2[i2][0] = ffma2(a2[i2], b0, oacc2[i2][0]);
                oacc2[i2][1] = ffma2(a2[i2], b1, oacc2[i2][1]);
                oacc2[i2][2] = ffma2(a2[i2], b2, oacc2[i2][2]);
                oacc2[i2][3] = ffma2(a2[i2], b3, oacc2[i2][3]);
            }
        }
    }

#pragma unroll
    for (int i2 = 0; i2 < 4; i2++) {
        float2 c0v = unpack2(oacc2[i2][0]);
        float2 c1v = unpack2(oacc2[i2][1]);
        float2 c2v = unpack2(oacc2[i2][2]);
        float2 c3v = unpack2(oacc2[i2][3]);
        const int q0 = qbase + ty * 8 + i2 * 2;
        *(float4*)&out[((size_t)b * SS + q0) * DD + h * HD + tx * 4] =
            make_float4(c0v.x, c1v.x, c2v.x, c3v.x);
        *(float4*)&out[((size_t)b * SS + q0 + 1) * DD + h * HD + tx * 4] =
            make_float4(c0v.y, c1v.y, c2v.y, c3v.y);
    }
}

// ---------------------------------------------------------------------------
extern "C" void kernel_launch(void* const* d_in, const int* in_sizes, int n_in,
                              void* d_out, int out_size)
{
    const float* query = (const float*)d_in[0];
    const float* key_t = (const float*)d_in[1];
    const float* value = (const float*)d_in[2];
    const float* rel   = (const float*)d_in[3];
    const unsigned int* mask = (const unsigned int*)d_in[4];
    const float* l1    = (const float*)d_in[5];
    const float* Wq = (const float*)d_in[6];
    const float* bq = (const float*)d_in[7];
    const float* Wk = (const float*)d_in[8];
    const float* bk = (const float*)d_in[9];
    const float* Wv = (const float*)d_in[10];
    const float* bv = (const float*)d_in[11];

    float* out  = (float*)d_out;
    float* prob = out + (size_t)BB * SS * DD;   // tuple layout: out, then prob_attn

    float *pq, *pk, *pv, *prel, *pl;
    cudaGetSymbolAddress((void**)&pq,   g_q);
    cudaGetSymbolAddress((void**)&pk,   g_k);
    cudaGetSymbolAddress((void**)&pv,   g_v);
    cudaGetSymbolAddress((void**)&prel, g_rel);
    cudaGetSymbolAddress((void**)&pl,   g_l);

    dim3 pg(DD / 128, (BB * SS) / 128);
    proj_kernel<<<pg, 256>>>(query, Wq, bq, pq);
    proj_kernel<<<pg, 256>>>(key_t, Wk, bk, pk);
    proj_kernel<<<pg, 256>>>(value, Wv, bv, pv);

    rel_softmax_kernel<<<BB * SS, 256>>>(rel, mask, prel);

    cudaFuncSetAttribute(qk_kernel,
                         cudaFuncAttributeMaxDynamicSharedMemorySize, QK_SMEM);
    qk_kernel<<<dim3(8, HH, BB), 256, QK_SMEM>>>(pq, pk, mask, prob, pl);

    cudaFuncSetAttribute(pv_kernel,
                         cudaFuncAttributeMaxDynamicSharedMemorySize, PV_SMEM);
    pv_kernel<<<dim3(8, HH, BB), 256, PV_SMEM>>>(pl, prel, pv, l1, out, prob);
}

// round 8
// speedup vs baseline: 2.6719x; 2.6719x over previous
#include <cuda_runtime.h>
#include <cuda_bf16.h>
#include <cstdint>

// Problem constants
#define BB 8
#define SS 1024
#define DD 768
#define HH 12
#define HD 64

// Scratch: projected q,k (B,H,S,HD), v transposed (B,H,HD,S), rel_attn, row sums
__device__ float g_q[BB * HH * SS * HD];      // 24 MB
__device__ float g_k[BB * HH * SS * HD];      // 24 MB
__device__ float g_vT[BB * HH * HD * SS];     // 24 MB (d-major for PV B-operand)
__device__ float g_rel[BB * SS * SS];         // 32 MB
__device__ float g_l[BB * HH * SS];           // 384 KB (softmax denominators)

// ---- tf32 mma helpers ------------------------------------------------------
__device__ __forceinline__ uint32_t f2tf(float f) {
    uint32_t r;
    asm("cvt.rna.tf32.f32 %0, %1;" : "=r"(r) : "f"(f));
    return r;
}
__device__ __forceinline__ void sts_tf32(uint32_t* p, float4 v) {
    uint4 u;
    u.x = f2tf(v.x); u.y = f2tf(v.y); u.z = f2tf(v.z); u.w = f2tf(v.w);
    *(uint4*)p = u;
}
__device__ __forceinline__ void mma8(float* d, const uint32_t* a, const uint32_t* b) {
    asm("mma.sync.aligned.m16n8k8.row.col.f32.tf32.tf32.f32 "
        "{%0,%1,%2,%3}, {%4,%5,%6,%7}, {%8,%9}, {%0,%1,%2,%3};"
        : "+f"(d[0]), "+f"(d[1]), "+f"(d[2]), "+f"(d[3])
        : "r"(a[0]), "r"(a[1]), "r"(a[2]), "r"(a[3]), "r"(b[0]), "r"(b[1]));
}

// ---------------------------------------------------------------------------
// Projection GEMM (tf32 MMA): Y[i,j] = sum_k X[i,k] * W[j,k] + b[j]
// Block 128x128, BK=16, 8 warps (2x4), warp tile 64x32.
// vtFlag=0: write (B,H,S,HD).  vtFlag=1: write transposed (B,H,HD,S).
// ---------------------------------------------------------------------------
__global__ __launch_bounds__(256) void proj_mma(
    const float* __restrict__ X, const float* __restrict__ W,
    const float* __restrict__ bias, float* __restrict__ out, int vtFlag)
{
    __shared__ uint32_t As[128][20];   // stride 20 == 4 mod 32: frag LDS conflict-free
    __shared__ uint32_t Bs[128][20];

    const int t    = threadIdx.x;
    const int lane = t & 31;
    const int wid  = t >> 5;
    const int grp  = lane >> 2;
    const int tig  = lane & 3;
    const int wm   = wid >> 2;         // 0..1
    const int wn   = wid & 3;          // 0..3
    const int bm   = blockIdx.y * 128;
    const int bn   = blockIdx.x * 128;

    float acc[4][4][4];
#pragma unroll
    for (int mt = 0; mt < 4; mt++)
#pragma unroll
        for (int nt = 0; nt < 4; nt++)
#pragma unroll
            for (int r = 0; r < 4; r++) acc[mt][nt][r] = 0.f;

    const int lr = t >> 2;            // 0..63
    const int lc = (t & 3) * 4;       // 0,4,8,12
    const float* xp0 = X + (size_t)(bm + lr) * DD + lc;
    const float* xp1 = xp0 + (size_t)64 * DD;
    const float* wp0 = W + (size_t)(bn + lr) * DD + lc;
    const float* wp1 = wp0 + (size_t)64 * DD;

    float4 xa0 = *(const float4*)xp0;
    float4 xa1 = *(const float4*)xp1;
    float4 wb0 = *(const float4*)wp0;
    float4 wb1 = *(const float4*)wp1;

    for (int k0 = 0; k0 < DD; k0 += 16) {
        sts_tf32(&As[lr][lc],      xa0);
        sts_tf32(&As[lr + 64][lc], xa1);
        sts_tf32(&Bs[lr][lc],      wb0);
        sts_tf32(&Bs[lr + 64][lc], wb1);
        __syncthreads();

        if (k0 + 16 < DD) {
            xa0 = *(const float4*)(xp0 + k0 + 16);
            xa1 = *(const float4*)(xp1 + k0 + 16);
            wb0 = *(const float4*)(wp0 + k0 + 16);
            wb1 = *(const float4*)(wp1 + k0 + 16);
        }

#pragma unroll
        for (int ks = 0; ks < 16; ks += 8) {
            uint32_t a[4][4], bq[4][2];
#pragma unroll
            for (int mt = 0; mt < 4; mt++) {
                const int m = wm * 64 + mt * 16;
                a[mt][0] = As[m + grp][ks + tig];
                a[mt][1] = As[m + grp + 8][ks + tig];
                a[mt][2] = As[m + grp][ks + tig + 4];
                a[mt][3] = As[m + grp + 8][ks + tig + 4];
            }
#pragma unroll
            for (int nt = 0; nt < 4; nt++) {
                const int n = wn * 32 + nt * 8;
                bq[nt][0] = Bs[n + grp][ks + tig];
                bq[nt][1] = Bs[n + grp][ks + tig + 4];
            }
#pragma unroll
            for (int mt = 0; mt < 4; mt++)
#pragma unroll
                for (int nt = 0; nt < 4; nt++)
                    mma8(acc[mt][nt], a[mt], bq[nt]);
        }
        __syncthreads();
    }

#pragma unroll
    for (int mt = 0; mt < 4; mt++) {
        const int row0 = bm + wm * 64 + mt * 16 + grp;
#pragma unroll
        for (int nt = 0; nt < 4; nt++) {
            const int col = bn + wn * 32 + nt * 8 + 2 * tig;
            const int h = col >> 6, d = col & 63;
            const float bi0 = bias[col], bi1 = bias[col + 1];
#pragma unroll
            for (int rr = 0; rr < 2; rr++) {
                const int row = row0 + 8 * rr;
                const int b = row >> 10, s = row & 1023;
                const float v0 = acc[mt][nt][2 * rr]     + bi0;
                const float v1 = acc[mt][nt][2 * rr + 1] + bi1;
                if (!vtFlag) {
                    *(float2*)&out[(((size_t)b * HH + h) * SS + s) * HD + d] =
                        make_float2(v0, v1);
                } else {
                    out[(((size_t)b * HH + h) * HD + d)     * SS + s] = v0;
                    out[(((size_t)b * HH + h) * HD + d + 1) * SS + s] = v1;
                }
            }
        }
    }
}

// ---------------------------------------------------------------------------
// rel_attn = softmax over k of (mask ? rel : -1e4).  (head-independent)
// ---------------------------------------------------------------------------
__global__ __launch_bounds__(256) void rel_softmax_kernel(
    const float* __restrict__ rel, const unsigned int* __restrict__ mask,
    float* __restrict__ outr)
{
    const int row = blockIdx.x;
    const float* r        = rel  + (size_t)row * SS;
    const unsigned int* m = mask + (size_t)row * SS;
    float* o              = outr + (size_t)row * SS;

    __shared__ float redmax[8], redsum[8];
    const int t = threadIdx.x;

    float v[4];
    float mx = -3.4e38f;
#pragma unroll
    for (int i = 0; i < 4; i++) {
        const int c = i * 256 + t;
        v[i] = m[c] ? r[c] : -1e4f;
        mx = fmaxf(mx, v[i]);
    }
#pragma unroll
    for (int o2 = 16; o2; o2 >>= 1) mx = fmaxf(mx, __shfl_xor_sync(0xffffffffu, mx, o2));
    if ((t & 31) == 0) redmax[t >> 5] = mx;
    __syncthreads();
    mx = redmax[0];
#pragma unroll
    for (int w = 1; w < 8; w++) mx = fmaxf(mx, redmax[w]);

    float sum = 0.f;
#pragma unroll
    for (int i = 0; i < 4; i++) {
        v[i] = __expf(v[i] - mx);
        sum += v[i];
    }
#pragma unroll
    for (int o2 = 16; o2; o2 >>= 1) sum += __shfl_xor_sync(0xffffffffu, sum, o2);
    if ((t & 31) == 0) redsum[t >> 5] = sum;
    __syncthreads();
    sum = 0.f;
#pragma unroll
    for (int w = 0; w < 8; w++) sum += redsum[w];
    const float inv = 1.f / sum;

#pragma unroll
    for (int i = 0; i < 4; i++) {
        const int c = i * 256 + t;
        o[c] = v[i] * inv;
    }
}

// ---------------------------------------------------------------------------
// QK (tf32 MMA): one block per (b, h, 128-q tile).
// e = mask ? 0 : exp((q.k)/8) (no max shift: |s| <~ 2); e -> prob scratch;
// row sums -> g_l.
// ---------------------------------------------------------------------------
#define QKS 68
#define QK_SMEM (2 * 128 * QKS * 4)

__global__ __launch_bounds__(256) void qk_mma(
    const float* __restrict__ qg, const float* __restrict__ kg,
    const unsigned int* __restrict__ mask,
    float* __restrict__ eprob, float* __restrict__ lsum)
{
    extern __shared__ uint32_t qsm[];
    uint32_t (*Qs)[QKS] = (uint32_t(*)[QKS])qsm;
    uint32_t (*Ks)[QKS] = (uint32_t(*)[QKS])(qsm + 128 * QKS);
    __shared__ float lsum_s[128];

    const int t    = threadIdx.x;
    const int lane = t & 31;
    const int wid  = t >> 5;
    const int grp  = lane >> 2;
    const int tig  = lane & 3;
    const int wm   = wid >> 2;
    const int wn   = wid & 3;
    const int qt = blockIdx.x, h = blockIdx.y, b = blockIdx.z;
    const int bh = b * HH + h;
    const int qbase = qt * 128;

    if (t < 128) lsum_s[t] = 0.f;

    // stage Q (128 x 64) as tf32
    const float* Qg = qg + ((size_t)bh * SS + qbase) * HD;
#pragma unroll
    for (int i = 0; i < 8; i++) {
        const int f = t + 256 * i;
        const int r = f >> 4, c4 = (f & 15) * 4;
        sts_tf32(&Qs[r][c4], *(const float4*)(Qg + (size_t)r * HD + c4));
    }

    const float* Kg = kg + (size_t)bh * SS * HD;
    float rs[4][2];
#pragma unroll
    for (int mt = 0; mt < 4; mt++) { rs[mt][0] = 0.f; rs[mt][1] = 0.f; }

#pragma unroll 1
    for (int kt = 0; kt < 8; kt++) {
        __syncthreads();   // prev MMA reads done (covers Q stage + lsum_s init at kt=0)
#pragma unroll
        for (int i = 0; i < 8; i++) {
            const int f = t + 256 * i;
            const int r = f >> 4, c4 = (f & 15) * 4;
            sts_tf32(&Ks[r][c4],
                     *(const float4*)(Kg + (size_t)(kt * 128 + r) * HD + c4));
        }
        __syncthreads();

        float acc[4][4][4];
#pragma unroll
        for (int mt = 0; mt < 4; mt++)
#pragma unroll
            for (int nt = 0; nt < 4; nt++)
#pragma unroll
                for (int r = 0; r < 4; r++) acc[mt][nt][r] = 0.f;

#pragma unroll
        for (int k8 = 0; k8 < 8; k8++) {
            const int ks = 8 * k8;
            uint32_t a[4][4], bq[4][2];
#pragma unroll
            for (int mt = 0; mt < 4; mt++) {
                const int m = wm * 64 + mt * 16;
                a[mt][0] = Qs[m + grp][ks + tig];
                a[mt][1] = Qs[m + grp + 8][ks + tig];
                a[mt][2] = Qs[m + grp][ks + tig + 4];
                a[mt][3] = Qs[m + grp + 8][ks + tig + 4];
            }
#pragma unroll
            for (int nt = 0; nt < 4; nt++) {
                const int n = wn * 32 + nt * 8;
                bq[nt][0] = Ks[n + grp][ks + tig];
                bq[nt][1] = Ks[n + grp][ks + tig + 4];
            }
#pragma unroll
            for (int mt = 0; mt < 4; mt++)
#pragma unroll
                for (int nt = 0; nt < 4; nt++)
                    mma8(acc[mt][nt], a[mt], bq[nt]);
        }

        // epilogue: mask, exp, store e, accumulate row sums
#pragma unroll
        for (int mt = 0; mt < 4; mt++) {
            const int q0 = qbase + wm * 64 + mt * 16 + grp;
#pragma unroll
            for (int nt = 0; nt < 4; nt++) {
                const int c = kt * 128 + wn * 32 + nt * 8 + 2 * tig;
                const uint2 ma = *(const uint2*)&mask[((size_t)b * SS + q0) * SS + c];
                const uint2 mb = *(const uint2*)&mask[((size_t)b * SS + q0 + 8) * SS + c];
                const float e00 = ma.x ? 0.f : __expf(acc[mt][nt][0] * 0.125f);
                const float e01 = ma.y ? 0.f : __expf(acc[mt][nt][1] * 0.125f);
                const float e10 = mb.x ? 0.f : __expf(acc[mt][nt][2] * 0.125f);
                const float e11 = mb.y ? 0.f : __expf(acc[mt][nt][3] * 0.125f);
                rs[mt][0] += e00 + e01;
                rs[mt][1] += e10 + e11;
                *(float2*)&eprob[((size_t)bh * SS + q0) * SS + c]     = make_float2(e00, e01);
                *(float2*)&eprob[((size_t)bh * SS + q0 + 8) * SS + c] = make_float2(e10, e11);
            }
        }
    }

    // reduce row sums: quad shuffle then smem atomics (4 n-warps share rows)
#pragma unroll
    for (int mt = 0; mt < 4; mt++)
#pragma unroll
        for (int rr = 0; rr < 2; rr++) {
            float v = rs[mt][rr];
            v += __shfl_xor_sync(0xffffffffu, v, 1);
            v += __shfl_xor_sync(0xffffffffu, v, 2);
            if (tig == 0)
                atomicAdd(&lsum_s[wm * 64 + mt * 16 + grp + 8 * rr], v);
        }
    __syncthreads();
    if (t < 128) lsum[(size_t)bh * SS + qbase + t] = lsum_s[t];
}

// ---------------------------------------------------------------------------
// PV (tf32 MMA): blend p = c0*e/l + l1*rel in place into prob (fp32 exact),
// then O = P @ V with P staged tf32 and V read from the d-major g_vT.
// ---------------------------------------------------------------------------
#define PVS 68
#define PV_SMEM ((128 + 64) * PVS * 4)

__global__ __launch_bounds__(256) void pv_mma(
    const float* __restrict__ lsum, const float* __restrict__ relattn,
    const float* __restrict__ vT, const float* __restrict__ l1p,
    float* __restrict__ out, float* __restrict__ prob)
{
    extern __shared__ uint32_t psm[];
    uint32_t (*Ps)[PVS] = (uint32_t(*)[PVS])psm;            // [128][68]
    uint32_t (*Vs)[PVS] = (uint32_t(*)[PVS])(psm + 128 * PVS); // [64][68]
    __shared__ float invl_s[128];

    const int t    = threadIdx.x;
    const int lane = t & 31;
    const int wid  = t >> 5;
    const int grp  = lane >> 2;
    const int tig  = lane & 3;
    const int wm   = wid >> 2;
    const int wn   = wid & 3;
    const int qt = blockIdx.x, h = blockIdx.y, b = blockIdx.z;
    const int bh = b * HH + h;
    const int qbase = qt * 128;

    const float l1 = *l1p;
    const float c0 = 1.f - l1;

    if (t < 128) invl_s[t] = 1.f / lsum[(size_t)bh * SS + qbase + t];
    __syncthreads();

    float acc[4][2][4];
#pragma unroll
    for (int mt = 0; mt < 4; mt++)
#pragma unroll
        for (int nt = 0; nt < 2; nt++)
#pragma unroll
            for (int r = 0; r < 4; r++) acc[mt][nt][r] = 0.f;

#pragma unroll 1
    for (int kt = 0; kt < 16; kt++) {
        if (kt) __syncthreads();
        // blend + prob write + stage P (128 rows x 64 k)
#pragma unroll
        for (int i = 0; i < 8; i++) {
            const int f = t + 256 * i;
            const int r = f >> 4, c4 = (f & 15) * 4;
            const int kc = kt * 64 + c4;
            float* erow       = prob    + ((size_t)bh * SS + qbase + r) * SS;
            const float* rrow = relattn + ((size_t)b  * SS + qbase + r) * SS;
            const float iv = invl_s[r];
            const float4 e4 = *(const float4*)(erow + kc);
            const float4 r4 = *(const float4*)(rrow + kc);
            float4 p4;
            p4.x = c0 * e4.x * iv + l1 * r4.x;
            p4.y = c0 * e4.y * iv + l1 * r4.y;
            p4.z = c0 * e4.z * iv + l1 * r4.z;
            p4.w = c0 * e4.w * iv + l1 * r4.w;
            *(float4*)(erow + kc) = p4;
            sts_tf32(&Ps[r][c4], p4);
        }
        // stage V (64 d rows x 64 k) from d-major vT — coalesced, no transpose
#pragma unroll
        for (int i = 0; i < 4; i++) {
            const int f = t + 256 * i;
            const int d = f >> 4, c4 = (f & 15) * 4;
            sts_tf32(&Vs[d][c4],
                     *(const float4*)(vT + ((size_t)bh * HD + d) * SS + kt * 64 + c4));
        }
        __syncthreads();

#pragma unroll
        for (int k8 = 0; k8 < 8; k8++) {
            const int ks = 8 * k8;
            uint32_t a[4][4], bq[2][2];
#pragma unroll
            for (int mt = 0; mt < 4; mt++) {
                const int m = wm * 64 + mt * 16;
                a[mt][0] = Ps[m + grp][ks + tig];
                a[mt][1] = Ps[m + grp + 8][ks + tig];
                a[mt][2] = Ps[m + grp][ks + tig + 4];
                a[mt][3] = Ps[m + grp + 8][ks + tig + 4];
            }
#pragma unroll
            for (int nt = 0; nt < 2; nt++) {
                const int n = wn * 16 + nt * 8;
                bq[nt][0] = Vs[n + grp][ks + tig];
                bq[nt][1] = Vs[n + grp][ks + tig + 4];
            }
#pragma unroll
            for (int mt = 0; mt < 4; mt++)
#pragma unroll
                for (int nt = 0; nt < 2; nt++)
                    mma8(acc[mt][nt], a[mt], bq[nt]);
        }
    }

#pragma unroll
    for (int mt = 0; mt < 4; mt++) {
        const int q0 = qbase + wm * 64 + mt * 16 + grp;
#pragma unroll
        for (int nt = 0; nt < 2; nt++) {
            const int d0 = wn * 16 + nt * 8 + 2 * tig;
            *(float2*)&out[((size_t)b * SS + q0) * DD + h * HD + d0] =
                make_float2(acc[mt][nt][0], acc[mt][nt][1]);
            *(float2*)&out[((size_t)b * SS + q0 + 8) * DD + h * HD + d0] =
                make_float2(acc[mt][nt][2], acc[mt][nt][3]);
        }
    }
}

// ---------------------------------------------------------------------------
extern "C" void kernel_launch(void* const* d_in, const int* in_sizes, int n_in,
                              void* d_out, int out_size)
{
    const float* query = (const float*)d_in[0];
    const float* key_t = (const float*)d_in[1];
    const float* value = (const float*)d_in[2];
    const float* rel   = (const float*)d_in[3];
    const unsigned int* mask = (const unsigned int*)d_in[4];
    const float* l1    = (const float*)d_in[5];
    const float* Wq = (const float*)d_in[6];
    const float* bq = (const float*)d_in[7];
    const float* Wk = (const float*)d_in[8];
    const float* bk = (const float*)d_in[9];
    const float* Wv = (const float*)d_in[10];
    const float* bv = (const float*)d_in[11];

    float* out  = (float*)d_out;
    float* prob = out + (size_t)BB * SS * DD;   // tuple layout: out, then prob_attn

    float *pq, *pk, *pvT, *prel, *pl;
    cudaGetSymbolAddress((void**)&pq,   g_q);
    cudaGetSymbolAddress((void**)&pk,   g_k);
    cudaGetSymbolAddress((void**)&pvT,  g_vT);
    cudaGetSymbolAddress((void**)&prel, g_rel);
    cudaGetSymbolAddress((void**)&pl,   g_l);

    dim3 pg(DD / 128, (BB * SS) / 128);
    proj_mma<<<pg, 256>>>(query, Wq, bq, pq,  0);
    proj_mma<<<pg, 256>>>(key_t, Wk, bk, pk,  0);
    proj_mma<<<pg, 256>>>(value, Wv, bv, pvT, 1);

    rel_softmax_kernel<<<BB * SS, 256>>>(rel, mask, prel);

    cudaFuncSetAttribute(qk_mma,
                         cudaFuncAttributeMaxDynamicSharedMemorySize, QK_SMEM);
    qk_mma<<<dim3(8, HH, BB), 256, QK_SMEM>>>(pq, pk, mask, prob, pl);

    cudaFuncSetAttribute(pv_mma,
                         cudaFuncAttributeMaxDynamicSharedMemorySize, PV_SMEM);
    pv_mma<<<dim3(8, HH, BB), 256, PV_SMEM>>>(pl, prel, pvT, l1, out, prob);
}